// round 13
// baseline (speedup 1.0000x reference)
#include <cuda_runtime.h>
#include <cuda_bf16.h>
#include <cstdint>
#include <math.h>

#define Nn 80000
#define Uu 40000
#define Dd 128
#define Ee 1600000
#define Lh 17   // K+1 keys
#define NnDd (Nn * Dd)

// ---------------- scratch (static device globals: no allocation) ----------------
__device__ float g_tmp[NnDd];                 // spmm output (fp32, exact residual path)
__device__ float g_e[NnDd];                   // e in fp32 (spmm gather source)
__device__ __nv_bfloat16 g_Qb[NnDd];          // Q projection (own set), bf16
__device__ __nv_bfloat16 g_KTb[2 * NnDd];     // K table per weight-set, bf16
__device__ __nv_bfloat16 g_VTb[2 * NnDd];     // V table per weight-set, bf16
__device__ float g_O[NnDd];                   // attention output, fp32
__device__ float g_total[NnDd];
__device__ float g_posK[2 * Lh * Dd];
__device__ float g_posV[2 * Lh * Dd];
__device__ float g_posQ0[2 * Dd];
__device__ int   g_cnt[Nn];                   // hist counter (zeroed by prev call's scan)
__device__ int   g_cnt2[Nn];                  // scatter counter (zeroed by this call's scan)
__device__ int   g_rowptr[Nn + 1];
__device__ int2  g_edge[Ee];                  // packed (col, val-as-int)
// 8 weight matrices split to bf16 {hi,lo}, plain row-major [128][128]
__device__ __nv_bfloat16 g_Bh[8 * 16384];
__device__ __nv_bfloat16 g_Bl[8 * 16384];

// ---------------- PTX helpers (baseline PTX only) ----------------
__device__ __forceinline__ uint32_t smem_to_u32(const void* p) {
    uint32_t a;
    asm("{ .reg .u64 tmp; cvta.to.shared.u64 tmp, %1; cvt.u32.u64 %0, tmp; }" : "=r"(a) : "l"(p));
    return a;
}
__device__ __forceinline__ void ldm4(uint32_t* r, uint32_t addr) {
    asm volatile("ldmatrix.sync.aligned.m8n8.x4.shared.b16 {%0,%1,%2,%3}, [%4];"
                 : "=r"(r[0]), "=r"(r[1]), "=r"(r[2]), "=r"(r[3]) : "r"(addr));
}
__device__ __forceinline__ void mma_bf16(float* c, const uint32_t* a, uint32_t b0, uint32_t b1) {
    asm volatile("mma.sync.aligned.m16n8k16.row.col.f32.bf16.bf16.f32 "
                 "{%0,%1,%2,%3}, {%4,%5,%6,%7}, {%8,%9}, {%0,%1,%2,%3};"
                 : "+f"(c[0]), "+f"(c[1]), "+f"(c[2]), "+f"(c[3])
                 : "r"(a[0]), "r"(a[1]), "r"(a[2]), "r"(a[3]), "r"(b0), "r"(b1));
}
__device__ __forceinline__ uint32_t lds32(uint32_t addr) {
    uint32_t v;
    asm volatile("ld.shared.b32 %0, [%1];" : "=r"(v) : "r"(addr));
    return v;
}

#define ASTRIDE 136   // bf16 elems per smem row (128 + 8 pad -> conflict-free ldmatrix)

// One pass over all 8 k-steps for one B flavor.  If alAddr != 0, also accumulates Al*B.
__device__ __forceinline__ void mma_phase(uint32_t ahAddr, uint32_t alAddr, uint32_t bAddr,
                                          int warp_m, int warp_n, int lane,
                                          float (*acc)[4]) {
    const int g = lane >> 2, q = lane & 3;
    const int arow = lane & 15, ahalf = (lane >> 4) << 3;
    #pragma unroll
    for (int ks = 0; ks < 8; ks++) {
        uint32_t b0[4], b1[4];
        #pragma unroll
        for (int tn = 0; tn < 4; tn++) {
            uint32_t baddr = bAddr + (uint32_t)(((warp_n * 32 + tn * 8 + g) * ASTRIDE + ks * 16 + 2 * q) << 1);
            b0[tn] = lds32(baddr);
            b1[tn] = lds32(baddr + 16);
        }
        #pragma unroll
        for (int tm = 0; tm < 4; tm++) {
            uint32_t a[4];
            uint32_t aaddr = ahAddr + (uint32_t)(((warp_m * 64 + tm * 16 + arow) * ASTRIDE + ks * 16 + ahalf) << 1);
            ldm4(a, aaddr);
            #pragma unroll
            for (int tn = 0; tn < 4; tn++) mma_bf16(acc[tm * 4 + tn], a, b0[tn], b1[tn]);
        }
        if (alAddr) {
            #pragma unroll
            for (int tm = 0; tm < 4; tm++) {
                uint32_t a[4];
                uint32_t aaddr = alAddr + (uint32_t)(((warp_m * 64 + tm * 16 + arow) * ASTRIDE + ks * 16 + ahalf) << 1);
                ldm4(a, aaddr);
                #pragma unroll
                for (int tn = 0; tn < 4; tn++) mma_bf16(acc[tm * 4 + tn], a, b0[tn], b1[tn]);
            }
        }
    }
}

// stage 128-row fp32 tile -> smem bf16 hi/lo (2 threads per row)
__device__ __forceinline__ void stage_A(__nv_bfloat16* AhS, __nv_bfloat16* AlS,
                                        const float* __restrict__ src128, int row0,
                                        int rowLimit, int t) {
    const int r = t >> 1, h = (t & 1) * 64;
    const bool valid = (row0 + r) < rowLimit;
    const float* src = &src128[(size_t)(row0 + r) * 128 + h];
    #pragma unroll
    for (int i = 0; i < 16; i++) {
        float4 v = valid ? *(const float4*)&src[i * 4] : make_float4(0.f, 0.f, 0.f, 0.f);
        __nv_bfloat16 h0 = __float2bfloat16(v.x), h1 = __float2bfloat16(v.y);
        __nv_bfloat16 h2 = __float2bfloat16(v.z), h3 = __float2bfloat16(v.w);
        __nv_bfloat16 l0 = __float2bfloat16(v.x - __bfloat162float(h0));
        __nv_bfloat16 l1 = __float2bfloat16(v.y - __bfloat162float(h1));
        __nv_bfloat16 l2 = __float2bfloat16(v.z - __bfloat162float(h2));
        __nv_bfloat16 l3 = __float2bfloat16(v.w - __bfloat162float(h3));
        int idx = r * ASTRIDE + h + i * 4;
        *(__nv_bfloat162*)&AhS[idx]     = __halves2bfloat162(h0, h1);
        *(__nv_bfloat162*)&AhS[idx + 2] = __halves2bfloat162(h2, h3);
        *(__nv_bfloat162*)&AlS[idx]     = __halves2bfloat162(l0, l1);
        *(__nv_bfloat162*)&AlS[idx + 2] = __halves2bfloat162(l2, l3);
    }
}

// stage 128-row fp32 tile -> smem bf16 hi ONLY (for single-pass GEMMs)
__device__ __forceinline__ void stage_Ah(__nv_bfloat16* AhS,
                                         const float* __restrict__ src128, int row0, int t) {
    const int r = t >> 1, h = (t & 1) * 64;
    const float* src = &src128[(size_t)(row0 + r) * 128 + h];
    #pragma unroll
    for (int i = 0; i < 16; i++) {
        float4 v = *(const float4*)&src[i * 4];
        __nv_bfloat16 h0 = __float2bfloat16(v.x), h1 = __float2bfloat16(v.y);
        __nv_bfloat16 h2 = __float2bfloat16(v.z), h3 = __float2bfloat16(v.w);
        int idx = r * ASTRIDE + h + i * 4;
        *(__nv_bfloat162*)&AhS[idx]     = __halves2bfloat162(h0, h1);
        *(__nv_bfloat162*)&AhS[idx + 2] = __halves2bfloat162(h2, h3);
    }
}

// stage 128x128 bf16 weight (plain row-major) -> padded smem
__device__ __forceinline__ void stage_B(__nv_bfloat16* BsS, const __nv_bfloat16* __restrict__ src, int t) {
    const int r = t >> 1, h = (t & 1) * 64;
    const uint4* s = (const uint4*)&src[r * 128 + h];
    #pragma unroll
    for (int i = 0; i < 8; i++)
        *(uint4*)&BsS[r * ASTRIDE + h + i * 8] = s[i];
}

// ---------------- init + hist: e/total init, histogram rows into g_cnt ----------
// g_cnt enters zeroed (previous call's k_scan zeroes it; zero-init at load).
__global__ void k_init(const float4* __restrict__ ue4, const float4* __restrict__ ie4,
                       const int* __restrict__ rows) {
    int i = blockIdx.x * blockDim.x + threadIdx.x;
    if (i < NnDd / 4) {
        float4 v = (i < Uu * Dd / 4) ? ue4[i] : ie4[i - Uu * Dd / 4];
        ((float4*)g_e)[i] = v;
        ((float4*)g_total)[i] = v;
    }
    if (i < Ee) atomicAdd(&g_cnt[rows[i]], 1);
}

// scan g_cnt -> rowptr; re-zero g_cnt (invariant for next call); zero g_cnt2 for scatter
__global__ void k_scan() {
    __shared__ int ssum[1024];
    const int t = threadIdx.x;
    const int CH = (Nn + 1023) / 1024;
    int lo = t * CH;
    int hi = lo + CH; if (hi > Nn) hi = Nn;
    if (lo > Nn) lo = Nn;
    int s = 0;
    for (int r = lo; r < hi; r++) s += g_cnt[r];
    ssum[t] = s;
    __syncthreads();
    for (int off = 1; off < 1024; off <<= 1) {
        int v = (t >= off) ? ssum[t - off] : 0;
        __syncthreads();
        ssum[t] += v;
        __syncthreads();
    }
    int base = (t == 0) ? 0 : ssum[t - 1];
    for (int r = lo; r < hi; r++) { g_rowptr[r] = base; base += g_cnt[r]; g_cnt[r] = 0; g_cnt2[r] = 0; }
    if (t == 1023) g_rowptr[Nn] = ssum[1023];
}
__global__ void k_scatter(const int* __restrict__ rows, const int* __restrict__ cols,
                          const float* __restrict__ vals) {
    int i = blockIdx.x * blockDim.x + threadIdx.x;
    if (i >= Ee) return;
    int r = rows[i];
    int p = g_rowptr[r] + atomicAdd(&g_cnt2[r], 1);
    g_edge[p] = make_int2(cols[i], __float_as_int(vals[i]));
}

// ---------------- SpMM (CSR, one warp per row, fp32 gathers, MLP-4) --------------
__global__ void __launch_bounds__(256) k_spmm() {
    int w = (blockIdx.x * 256 + threadIdx.x) >> 5;
    if (w >= Nn) return;
    int lane = threadIdx.x & 31;
    const int c4 = lane * 4;
    int j0 = g_rowptr[w], j1 = g_rowptr[w + 1];
    float4 acc = make_float4(0.f, 0.f, 0.f, 0.f);
    int j = j0;
    for (; j + 4 <= j1; j += 4) {
        int2 ed0 = g_edge[j],     ed1 = g_edge[j + 1];
        int2 ed2 = g_edge[j + 2], ed3 = g_edge[j + 3];
        float4 e0 = *(const float4*)&g_e[(size_t)ed0.x * Dd + c4];
        float4 e1 = *(const float4*)&g_e[(size_t)ed1.x * Dd + c4];
        float4 e2 = *(const float4*)&g_e[(size_t)ed2.x * Dd + c4];
        float4 e3 = *(const float4*)&g_e[(size_t)ed3.x * Dd + c4];
        float v0 = __int_as_float(ed0.y), v1 = __int_as_float(ed1.y);
        float v2 = __int_as_float(ed2.y), v3 = __int_as_float(ed3.y);
        acc.x += v0 * e0.x; acc.y += v0 * e0.y; acc.z += v0 * e0.z; acc.w += v0 * e0.w;
        acc.x += v1 * e1.x; acc.y += v1 * e1.y; acc.z += v1 * e1.z; acc.w += v1 * e1.w;
        acc.x += v2 * e2.x; acc.y += v2 * e2.y; acc.z += v2 * e2.z; acc.w += v2 * e2.w;
        acc.x += v3 * e3.x; acc.y += v3 * e3.y; acc.z += v3 * e3.z; acc.w += v3 * e3.w;
    }
    for (; j < j1; j++) {
        int2 ed = g_edge[j];
        float v = __int_as_float(ed.y);
        float4 ev = *(const float4*)&g_e[(size_t)ed.x * Dd + c4];
        acc.x += v * ev.x; acc.y += v * ev.y; acc.z += v * ev.z; acc.w += v * ev.w;
    }
    *(float4*)&g_tmp[w * Dd + c4] = acc;
}

// ---------------- projected positional embeddings (fp32) ----------------
__global__ void k_pos(const float* __restrict__ pos, const float* __restrict__ u_in_w,
                      const float* __restrict__ i_in_w) {
    int bid = blockIdx.x;
    int set = bid / 35;
    int r = bid % 35;
    const float* w = set ? i_in_w : u_in_w;
    const float* prow;
    float* out;
    if (r == 0)      { prow = pos;                 w += 0;           out = &g_posQ0[set * Dd]; }
    else if (r < 18) { int l = r - 1;  prow = pos + l * Dd; w += Dd * Dd;     out = &g_posK[(set * Lh + l) * Dd]; }
    else             { int l = r - 18; prow = pos + l * Dd; w += 2 * Dd * Dd; out = &g_posV[(set * Lh + l) * Dd]; }
    __shared__ float p[Dd];
    p[threadIdx.x] = prow[threadIdx.x];
    __syncthreads();
    int j = threadIdx.x;
    float acc = 0.f;
    #pragma unroll 4
    for (int k = 0; k < Dd; k++) acc += p[k] * w[j * 128 + k];
    out[j] = acc;
}

// ---------------- weight prep: fp32 -> {hi,lo} bf16, plain row-major ------------
__global__ void k_prep(const float* __restrict__ u_in_w, const float* __restrict__ i_in_w,
                       const float* __restrict__ u_out_w, const float* __restrict__ i_out_w) {
    int m = blockIdx.x;
    const float* src;
    switch (m) {
        case 0: src = u_in_w; break;
        case 1: src = u_in_w + 16384; break;
        case 2: src = u_in_w + 32768; break;
        case 3: src = i_in_w; break;
        case 4: src = i_in_w + 16384; break;
        case 5: src = i_in_w + 32768; break;
        case 6: src = u_out_w; break;
        default: src = i_out_w; break;
    }
    for (int idx = threadIdx.x; idx < 16384; idx += 256) {
        float x = src[idx];
        __nv_bfloat16 h = __float2bfloat16(x);
        __nv_bfloat16 l = __float2bfloat16(x - __bfloat162float(h));
        g_Bh[m * 16384 + idx] = h;
        g_Bl[m * 16384 + idx] = l;
    }
}

// ---------------- fused in-projection: single-pass bf16, all outputs bf16 -------
// j: 0=Qu 1=Ku 2=Vu 3=Qi 4=Ki 5=Vi.  Pure-set tiles skip the other set's Q.
// smem: Ah[128][136] + Bs[128][136] bf16 = 69632 B -> 3 CTAs/SM
__global__ void __launch_bounds__(256) k_mma_in(const float* __restrict__ u_in_b,
                                                const float* __restrict__ i_in_b) {
    extern __shared__ __align__(16) __nv_bfloat16 smp[];
    __nv_bfloat16* AhS = smp;
    __nv_bfloat16* BsS = smp + 128 * ASTRIDE;
    const uint32_t ahA = smem_to_u32(AhS), bA = smem_to_u32(BsS);
    const int t = threadIdx.x, lane = t & 31, wid = t >> 5;
    const int warp_m = wid >> 2, warp_n = wid & 3;
    const int row0 = blockIdx.x * 128;

    int skipj = -1;
    if (row0 + 128 <= Uu) skipj = 3;        // pure user tile: no Qi
    else if (row0 >= Uu)  skipj = 0;        // pure item tile: no Qu

    stage_Ah(AhS, g_tmp, row0, t);

    for (int j = 0; j < 6; j++) {
        if (j == skipj) continue;
        float acc[16][4];
        #pragma unroll
        for (int i = 0; i < 16; i++) { acc[i][0] = 0.f; acc[i][1] = 0.f; acc[i][2] = 0.f; acc[i][3] = 0.f; }

        __syncthreads();
        stage_B(BsS, &g_Bh[j * 16384], t);
        __syncthreads();
        mma_phase(ahA, 0, bA, warp_m, warp_n, lane, acc);   // single-pass AhBh

        const float* bias;
        __nv_bfloat16* outB;
        int qKind = -1;
        switch (j) {
            case 0: bias = u_in_b;        outB = g_Qb;        qKind = 0; break;
            case 1: bias = u_in_b + 128;  outB = g_KTb;       break;
            case 2: bias = u_in_b + 256;  outB = g_VTb;       break;
            case 3: bias = i_in_b;        outB = g_Qb;        qKind = 1; break;
            case 4: bias = i_in_b + 128;  outB = g_KTb + NnDd; break;
            default: bias = i_in_b + 256; outB = g_VTb + NnDd; break;
        }
        const int g = lane >> 2, q = lane & 3;
        #pragma unroll
        for (int tm = 0; tm < 4; tm++) {
            #pragma unroll
            for (int tn = 0; tn < 4; tn++) {
                int c_ = warp_n * 32 + tn * 8 + 2 * q;
                float2 bv = *(const float2*)&bias[c_];
                float* a4 = acc[tm * 4 + tn];
                #pragma unroll
                for (int hrow = 0; hrow < 2; hrow++) {
                    int r_ = row0 + warp_m * 64 + tm * 16 + g + hrow * 8;
                    if (qKind >= 0) {
                        bool ok = qKind ? (r_ >= Uu) : (r_ < Uu);
                        if (!ok) continue;
                    }
                    float ox = a4[hrow * 2 + 0] + bv.x;
                    float oy = a4[hrow * 2 + 1] + bv.y;
                    size_t ofs = (size_t)r_ * 128 + c_;
                    __nv_bfloat162 p = __halves2bfloat162(__float2bfloat16(ox), __float2bfloat16(oy));
                    *(__nv_bfloat162*)&outB[ofs] = p;
                }
            }
        }
    }
}

// ---------------- out-projection + residual + total; optional final output ------
// 2-pass split (AhBh + AlBh; weight-lo term dropped, ~1e-4 rel contribution).
// smem: Ah + Al + Bs = 104448 B
__global__ void __launch_bounds__(256) k_mma_out(const float* __restrict__ u_out_b,
                                                 const float* __restrict__ i_out_b,
                                                 float* __restrict__ finalOut) {
    extern __shared__ __align__(16) __nv_bfloat16 smp[];
    __nv_bfloat16* AhS = smp;
    __nv_bfloat16* AlS = smp + 128 * ASTRIDE;
    __nv_bfloat16* BsS = smp + 2 * 128 * ASTRIDE;
    const uint32_t ahA = smem_to_u32(AhS), alA = smem_to_u32(AlS), bA = smem_to_u32(BsS);
    const int t = threadIdx.x, lane = t & 31, wid = t >> 5;
    const int warp_m = wid >> 2, warp_n = wid & 3;

    const int set = (blockIdx.x >= 313) ? 1 : 0;
    const int bb = set ? (blockIdx.x - 313) : blockIdx.x;
    const int row0 = set * Uu + bb * 128;
    const int limit = set ? Nn : Uu;
    const int m = 6 + set;
    const float* bias = set ? i_out_b : u_out_b;

    stage_A(AhS, AlS, g_O, row0, limit, t);

    float acc[16][4];
    #pragma unroll
    for (int i = 0; i < 16; i++) { acc[i][0] = 0.f; acc[i][1] = 0.f; acc[i][2] = 0.f; acc[i][3] = 0.f; }

    stage_B(BsS, &g_Bh[m * 16384], t);
    __syncthreads();
    mma_phase(ahA, alA, bA, warp_m, warp_n, lane, acc);   // AhBh + AlBh

    const int g = lane >> 2, q = lane & 3;
    #pragma unroll
    for (int tm = 0; tm < 4; tm++) {
        #pragma unroll
        for (int tn = 0; tn < 4; tn++) {
            int c_ = warp_n * 32 + tn * 8 + 2 * q;
            float2 bv = *(const float2*)&bias[c_];
            float* a4 = acc[tm * 4 + tn];
            #pragma unroll
            for (int hrow = 0; hrow < 2; hrow++) {
                int r_ = row0 + warp_m * 64 + tm * 16 + g + hrow * 8;
                if (r_ >= limit) continue;
                size_t ofs = (size_t)r_ * 128 + c_;
                float2 rs = *(const float2*)&g_tmp[ofs];
                float ox = a4[hrow * 2 + 0] + bv.x + rs.x;
                float oy = a4[hrow * 2 + 1] + bv.y + rs.y;
                float2 tv = *(const float2*)&g_total[ofs];
                tv.x += ox; tv.y += oy;
                if (finalOut) {
                    *(float2*)&finalOut[ofs] = tv;
                    *(float2*)&finalOut[NnDd + ofs] = tv;
                } else {
                    *(float2*)&g_e[ofs] = make_float2(ox, oy);
                    *(float2*)&g_total[ofs] = tv;
                }
            }
        }
    }
}

// ---------------- attention: one warp per node; bf16 Q/K/V ----------------
__global__ void __launch_bounds__(256) k_attn(const int* __restrict__ samples) {
    int w = (blockIdx.x * 256 + threadIdx.x) >> 5;
    if (w >= Nn) return;
    int lane = threadIdx.x & 31;
    int set = (w < Uu) ? 0 : 1;
    const __nv_bfloat16* Kt = &g_KTb[(size_t)set * NnDd];
    const __nv_bfloat16* Vt = &g_VTb[(size_t)set * NnDd];
    const float* pk = &g_posK[set * Lh * Dd];
    const float* pv = &g_posV[set * Lh * Dd];
    const float* pq = &g_posQ0[set * Dd];
    int c4 = lane * 4;

    uint2 qu = *(const uint2*)&g_Qb[(size_t)w * Dd + c4];
    float2 q0 = __bfloat1622float2(*(__nv_bfloat162*)&qu.x);
    float2 q1 = __bfloat1622float2(*(__nv_bfloat162*)&qu.y);
    float4 pqv = *(const float4*)&pq[c4];
    float qx = q0.x + pqv.x, qy = q0.y + pqv.y, qz = q1.x + pqv.z, qw = q1.y + pqv.w;

    int sidx[Lh];
    sidx[0] = w;
    #pragma unroll
    for (int l = 1; l < Lh; l++) sidx[l] = samples[w * 16 + (l - 1)];

    const float scale = 0.17677669529663687f;
    float sc[Lh];
    #pragma unroll
    for (int b = 0; b < 4; b++) {
        uint2 ku[4]; float4 pk4[4];
        #pragma unroll
        for (int i = 0; i < 4; i++) {
            int l = b * 4 + i;
            ku[i] = *(const uint2*)&Kt[(size_t)sidx[l] * Dd + c4];
            pk4[i] = *(const float4*)&pk[l * Dd + c4];
        }
        #pragma unroll
        for (int i = 0; i < 4; i++) {
            float2 f0 = __bfloat1622float2(*(__nv_bfloat162*)&ku[i].x);
            float2 f1 = __bfloat1622float2(*(__nv_bfloat162*)&ku[i].y);
            float d = qx * (f0.x + pk4[i].x) + qy * (f0.y + pk4[i].y)
                    + qz * (f1.x + pk4[i].z) + qw * (f1.y + pk4[i].w);
            d += __shfl_xor_sync(0xffffffffu, d, 1);
            d += __shfl_xor_sync(0xffffffffu, d, 2);
            d += __shfl_xor_sync(0xffffffffu, d, 4);
            sc[b * 4 + i] = d * scale;
        }
    }
    {
        uint2 u = *(const uint2*)&Kt[(size_t)sidx[16] * Dd + c4];
        float4 pkv = *(const float4*)&pk[16 * Dd + c4];
        float2 f0 = __bfloat1622float2(*(__nv_bfloat162*)&u.x);
        float2 f1 = __bfloat1622float2(*(__nv_bfloat162*)&u.y);
        float d = qx * (f0.x + pkv.x) + qy * (f0.y + pkv.y) + qz * (f1.x + pkv.z) + qw * (f1.y + pkv.w);
        d += __shfl_xor_sync(0xffffffffu, d, 1);
        d += __shfl_xor_sync(0xffffffffu, d, 2);
        d += __shfl_xor_sync(0xffffffffu, d, 4);
        sc[16] = d * scale;
    }
    float m = sc[0];
    #pragma unroll
    for (int l = 1; l < Lh; l++) m = fmaxf(m, sc[l]);
    float s = 0.f;
    #pragma unroll
    for (int l = 0; l < Lh; l++) { sc[l] = __expf(sc[l] - m); s += sc[l]; }
    float inv = 1.f / s;

    float ox = 0.f, oy = 0.f, oz = 0.f, ow = 0.f;
    #pragma unroll
    for (int b = 0; b < 4; b++) {
        uint2 vu[4]; float4 pv4[4];
        #pragma unroll
        for (int i = 0; i < 4; i++) {
            int l = b * 4 + i;
            vu[i] = *(const uint2*)&Vt[(size_t)sidx[l] * Dd + c4];
            pv4[i] = *(const float4*)&pv[l * Dd + c4];
        }
        #pragma unroll
        for (int i = 0; i < 4; i++) {
            float wgt = sc[b * 4 + i] * inv;
            float2 f0 = __bfloat1622float2(*(__nv_bfloat162*)&vu[i].x);
            float2 f1 = __bfloat1622float2(*(__nv_bfloat162*)&vu[i].y);
            ox += wgt * (f0.x + pv4[i].x); oy += wgt * (f0.y + pv4[i].y);
            oz += wgt * (f1.x + pv4[i].z); ow += wgt * (f1.y + pv4[i].w);
        }
    }
    {
        float wgt = sc[16] * inv;
        uint2 u = *(const uint2*)&Vt[(size_t)sidx[16] * Dd + c4];
        float4 pvv = *(const float4*)&pv[16 * Dd + c4];
        float2 f0 = __bfloat1622float2(*(__nv_bfloat162*)&u.x);
        float2 f1 = __bfloat1622float2(*(__nv_bfloat162*)&u.y);
        ox += wgt * (f0.x + pvv.x); oy += wgt * (f0.y + pvv.y);
        oz += wgt * (f1.x + pvv.z); ow += wgt * (f1.y + pvv.w);
    }
    *(float4*)&g_O[w * Dd + c4] = make_float4(ox, oy, oz, ow);
}

extern "C" void kernel_launch(void* const* d_in, const int* in_sizes, int n_in,
                              void* d_out, int out_size) {
    (void)in_sizes; (void)n_in; (void)out_size;
    const int*   adj_rows = (const int*)d_in[0];
    const int*   adj_cols = (const int*)d_in[1];
    const float* adj_vals = (const float*)d_in[2];
    const int*   samples  = (const int*)d_in[3];
    const float* user_emb = (const float*)d_in[4];
    const float* item_emb = (const float*)d_in[5];
    const float* pos_emb  = (const float*)d_in[6];
    const float* u_in_w   = (const float*)d_in[7];
    const float* u_in_b   = (const float*)d_in[8];
    const float* u_out_w  = (const float*)d_in[9];
    const float* u_out_b  = (const float*)d_in[10];
    const float* i_in_w   = (const float*)d_in[11];
    const float* i_in_b   = (const float*)d_in[12];
    const float* i_out_w  = (const float*)d_in[13];
    const float* i_out_b  = (const float*)d_in[14];
    float* out = (float*)d_out;

    const int SMB_IN  = 2 * 128 * ASTRIDE * (int)sizeof(__nv_bfloat16);  // 69632
    const int SMB_OUT = 3 * 128 * ASTRIDE * (int)sizeof(__nv_bfloat16);  // 104448
    cudaFuncSetAttribute(k_mma_in,  cudaFuncAttributeMaxDynamicSharedMemorySize, SMB_IN);
    cudaFuncSetAttribute(k_mma_out, cudaFuncAttributeMaxDynamicSharedMemorySize, SMB_OUT);

    // launches: init+hist(1), scan(2), scatter(3), spmm(4=capture slot), ...
    k_init<<<(NnDd / 4 + 255) / 256, 256>>>((const float4*)user_emb, (const float4*)item_emb,
                                            adj_rows);
    k_scan<<<1, 1024>>>();
    k_scatter<<<(Ee + 255) / 256, 256>>>(adj_rows, adj_cols, adj_vals);

    for (int blk = 0; blk < 2; blk++) {
        k_spmm<<<(Nn * 32) / 256, 256>>>();
        if (blk == 0) {
            k_pos<<<70, 128>>>(pos_emb, u_in_w, i_in_w);
            k_prep<<<8, 256>>>(u_in_w, i_in_w, u_out_w, i_out_w);
        }
        k_mma_in<<<Nn / 128, 256, SMB_IN>>>(u_in_b, i_in_b);
        k_attn<<<(Nn * 32) / 256, 256>>>(samples);
        k_mma_out<<<626, 256, SMB_OUT>>>(u_out_b, i_out_b, (blk == 1) ? out : nullptr);
    }
}

// round 15
// speedup vs baseline: 1.5170x; 1.5170x over previous
#include <cuda_runtime.h>
#include <cuda_bf16.h>
#include <cstdint>
#include <math.h>

#define Nn 80000
#define Uu 40000
#define Dd 128
#define Ee 1600000
#define Lh 17   // K+1 keys
#define NnDd (Nn * Dd)

// ---------------- scratch (static device globals: no allocation) ----------------
__device__ float g_tmp[NnDd];                 // spmm output (fp32, exact residual path)
__device__ float g_e[NnDd];                   // e in fp32 (spmm gather source)
__device__ __nv_bfloat16 g_Qb[NnDd];          // Q projection (own set), bf16
__device__ __nv_bfloat16 g_KTb[2 * NnDd];     // K table per weight-set, bf16
__device__ __nv_bfloat16 g_VTb[2 * NnDd];     // V table per weight-set, bf16
__device__ float g_O[NnDd];                   // attention output, fp32
__device__ float g_total[NnDd];
__device__ float g_posK[2 * Lh * Dd];
__device__ float g_posV[2 * Lh * Dd];
__device__ float g_posQ0[2 * Dd];
__device__ int   g_cnt[Nn];
__device__ int   g_rowptr[Nn + 1];
__device__ int2  g_edge[Ee];                  // packed (col, val-as-int)
// 8 weight matrices split to bf16 {hi,lo}, plain row-major [128][128]
__device__ __nv_bfloat16 g_Bh[8 * 16384];
__device__ __nv_bfloat16 g_Bl[8 * 16384];

// ---------------- PTX helpers (baseline PTX only) ----------------
__device__ __forceinline__ uint32_t smem_to_u32(const void* p) {
    uint32_t a;
    asm("{ .reg .u64 tmp; cvta.to.shared.u64 tmp, %1; cvt.u32.u64 %0, tmp; }" : "=r"(a) : "l"(p));
    return a;
}
__device__ __forceinline__ void ldm4(uint32_t* r, uint32_t addr) {
    asm volatile("ldmatrix.sync.aligned.m8n8.x4.shared.b16 {%0,%1,%2,%3}, [%4];"
                 : "=r"(r[0]), "=r"(r[1]), "=r"(r[2]), "=r"(r[3]) : "r"(addr));
}
__device__ __forceinline__ void mma_bf16(float* c, const uint32_t* a, uint32_t b0, uint32_t b1) {
    asm volatile("mma.sync.aligned.m16n8k16.row.col.f32.bf16.bf16.f32 "
                 "{%0,%1,%2,%3}, {%4,%5,%6,%7}, {%8,%9}, {%0,%1,%2,%3};"
                 : "+f"(c[0]), "+f"(c[1]), "+f"(c[2]), "+f"(c[3])
                 : "r"(a[0]), "r"(a[1]), "r"(a[2]), "r"(a[3]), "r"(b0), "r"(b1));
}
__device__ __forceinline__ uint32_t lds32(uint32_t addr) {
    uint32_t v;
    asm volatile("ld.shared.b32 %0, [%1];" : "=r"(v) : "r"(addr));
    return v;
}

#define ASTRIDE 136   // bf16 elems per smem row (128 + 8 pad -> conflict-free ldmatrix)

// One pass over all 8 k-steps for one B flavor.  If alAddr != 0, also accumulates Al*B.
__device__ __forceinline__ void mma_phase(uint32_t ahAddr, uint32_t alAddr, uint32_t bAddr,
                                          int warp_m, int warp_n, int lane,
                                          float (*acc)[4]) {
    const int g = lane >> 2, q = lane & 3;
    const int arow = lane & 15, ahalf = (lane >> 4) << 3;
    #pragma unroll
    for (int ks = 0; ks < 8; ks++) {
        uint32_t b0[4], b1[4];
        #pragma unroll
        for (int tn = 0; tn < 4; tn++) {
            uint32_t baddr = bAddr + (uint32_t)(((warp_n * 32 + tn * 8 + g) * ASTRIDE + ks * 16 + 2 * q) << 1);
            b0[tn] = lds32(baddr);
            b1[tn] = lds32(baddr + 16);
        }
        #pragma unroll
        for (int tm = 0; tm < 4; tm++) {
            uint32_t a[4];
            uint32_t aaddr = ahAddr + (uint32_t)(((warp_m * 64 + tm * 16 + arow) * ASTRIDE + ks * 16 + ahalf) << 1);
            ldm4(a, aaddr);
            #pragma unroll
            for (int tn = 0; tn < 4; tn++) mma_bf16(acc[tm * 4 + tn], a, b0[tn], b1[tn]);
        }
        if (alAddr) {
            #pragma unroll
            for (int tm = 0; tm < 4; tm++) {
                uint32_t a[4];
                uint32_t aaddr = alAddr + (uint32_t)(((warp_m * 64 + tm * 16 + arow) * ASTRIDE + ks * 16 + ahalf) << 1);
                ldm4(a, aaddr);
                #pragma unroll
                for (int tn = 0; tn < 4; tn++) mma_bf16(acc[tm * 4 + tn], a, b0[tn], b1[tn]);
            }
        }
    }
}

// stage 128-row fp32 tile -> smem bf16 hi/lo (2 threads per row)
__device__ __forceinline__ void stage_A(__nv_bfloat16* AhS, __nv_bfloat16* AlS,
                                        const float* __restrict__ src128, int row0,
                                        int rowLimit, int t) {
    const int r = t >> 1, h = (t & 1) * 64;
    const bool valid = (row0 + r) < rowLimit;
    const float* src = &src128[(size_t)(row0 + r) * 128 + h];
    #pragma unroll
    for (int i = 0; i < 16; i++) {
        float4 v = valid ? *(const float4*)&src[i * 4] : make_float4(0.f, 0.f, 0.f, 0.f);
        __nv_bfloat16 h0 = __float2bfloat16(v.x), h1 = __float2bfloat16(v.y);
        __nv_bfloat16 h2 = __float2bfloat16(v.z), h3 = __float2bfloat16(v.w);
        __nv_bfloat16 l0 = __float2bfloat16(v.x - __bfloat162float(h0));
        __nv_bfloat16 l1 = __float2bfloat16(v.y - __bfloat162float(h1));
        __nv_bfloat16 l2 = __float2bfloat16(v.z - __bfloat162float(h2));
        __nv_bfloat16 l3 = __float2bfloat16(v.w - __bfloat162float(h3));
        int idx = r * ASTRIDE + h + i * 4;
        *(__nv_bfloat162*)&AhS[idx]     = __halves2bfloat162(h0, h1);
        *(__nv_bfloat162*)&AhS[idx + 2] = __halves2bfloat162(h2, h3);
        *(__nv_bfloat162*)&AlS[idx]     = __halves2bfloat162(l0, l1);
        *(__nv_bfloat162*)&AlS[idx + 2] = __halves2bfloat162(l2, l3);
    }
}

// stage 128-row fp32 tile -> smem bf16 hi ONLY (for single-pass GEMMs)
__device__ __forceinline__ void stage_Ah(__nv_bfloat16* AhS,
                                         const float* __restrict__ src128, int row0, int t) {
    const int r = t >> 1, h = (t & 1) * 64;
    const float* src = &src128[(size_t)(row0 + r) * 128 + h];
    #pragma unroll
    for (int i = 0; i < 16; i++) {
        float4 v = *(const float4*)&src[i * 4];
        __nv_bfloat16 h0 = __float2bfloat16(v.x), h1 = __float2bfloat16(v.y);
        __nv_bfloat16 h2 = __float2bfloat16(v.z), h3 = __float2bfloat16(v.w);
        int idx = r * ASTRIDE + h + i * 4;
        *(__nv_bfloat162*)&AhS[idx]     = __halves2bfloat162(h0, h1);
        *(__nv_bfloat162*)&AhS[idx + 2] = __halves2bfloat162(h2, h3);
    }
}

// stage 128x128 bf16 weight (plain row-major) -> padded smem
__device__ __forceinline__ void stage_B(__nv_bfloat16* BsS, const __nv_bfloat16* __restrict__ src, int t) {
    const int r = t >> 1, h = (t & 1) * 64;
    const uint4* s = (const uint4*)&src[r * 128 + h];
    #pragma unroll
    for (int i = 0; i < 8; i++)
        *(uint4*)&BsS[r * ASTRIDE + h + i * 8] = s[i];
}

// ---------------- init: e/total = concat(user,item); zero g_cnt -----------------
__global__ void k_init(const float4* __restrict__ ue4, const float4* __restrict__ ie4) {
    int i = blockIdx.x * blockDim.x + threadIdx.x;
    if (i >= NnDd / 4) return;
    float4 v = (i < Uu * Dd / 4) ? ue4[i] : ie4[i - Uu * Dd / 4];
    ((float4*)g_e)[i] = v;
    ((float4*)g_total)[i] = v;
    if (i < Nn) g_cnt[i] = 0;
}

// ---------------- CSR build ----------------
__global__ void k_hist(const int* __restrict__ rows) {
    int i = blockIdx.x * blockDim.x + threadIdx.x;
    if (i < Ee) atomicAdd(&g_cnt[rows[i]], 1);
}
// scan g_cnt -> rowptr; re-zero g_cnt for k_scatter
__global__ void k_scan() {
    __shared__ int ssum[1024];
    const int t = threadIdx.x;
    const int CH = (Nn + 1023) / 1024;
    int lo = t * CH;
    int hi = lo + CH; if (hi > Nn) hi = Nn;
    if (lo > Nn) lo = Nn;
    int s = 0;
    for (int r = lo; r < hi; r++) s += g_cnt[r];
    ssum[t] = s;
    __syncthreads();
    for (int off = 1; off < 1024; off <<= 1) {
        int v = (t >= off) ? ssum[t - off] : 0;
        __syncthreads();
        ssum[t] += v;
        __syncthreads();
    }
    int base = (t == 0) ? 0 : ssum[t - 1];
    for (int r = lo; r < hi; r++) { g_rowptr[r] = base; base += g_cnt[r]; g_cnt[r] = 0; }
    if (t == 1023) g_rowptr[Nn] = ssum[1023];
}
__global__ void k_scatter(const int* __restrict__ rows, const int* __restrict__ cols,
                          const float* __restrict__ vals) {
    int i = blockIdx.x * blockDim.x + threadIdx.x;
    if (i >= Ee) return;
    int r = rows[i];
    int p = g_rowptr[r] + atomicAdd(&g_cnt[r], 1);
    g_edge[p] = make_int2(cols[i], __float_as_int(vals[i]));
}

// ---------------- SpMM (CSR, one warp per row, fp32 gathers, MLP-4) --------------
__global__ void __launch_bounds__(256) k_spmm() {
    int w = (blockIdx.x * 256 + threadIdx.x) >> 5;
    if (w >= Nn) return;
    int lane = threadIdx.x & 31;
    const int c4 = lane * 4;
    int j0 = g_rowptr[w], j1 = g_rowptr[w + 1];
    float4 acc = make_float4(0.f, 0.f, 0.f, 0.f);
    int j = j0;
    for (; j + 4 <= j1; j += 4) {
        int2 ed0 = g_edge[j],     ed1 = g_edge[j + 1];
        int2 ed2 = g_edge[j + 2], ed3 = g_edge[j + 3];
        float4 e0 = *(const float4*)&g_e[(size_t)ed0.x * Dd + c4];
        float4 e1 = *(const float4*)&g_e[(size_t)ed1.x * Dd + c4];
        float4 e2 = *(const float4*)&g_e[(size_t)ed2.x * Dd + c4];
        float4 e3 = *(const float4*)&g_e[(size_t)ed3.x * Dd + c4];
        float v0 = __int_as_float(ed0.y), v1 = __int_as_float(ed1.y);
        float v2 = __int_as_float(ed2.y), v3 = __int_as_float(ed3.y);
        acc.x += v0 * e0.x; acc.y += v0 * e0.y; acc.z += v0 * e0.z; acc.w += v0 * e0.w;
        acc.x += v1 * e1.x; acc.y += v1 * e1.y; acc.z += v1 * e1.z; acc.w += v1 * e1.w;
        acc.x += v2 * e2.x; acc.y += v2 * e2.y; acc.z += v2 * e2.z; acc.w += v2 * e2.w;
        acc.x += v3 * e3.x; acc.y += v3 * e3.y; acc.z += v3 * e3.z; acc.w += v3 * e3.w;
    }
    for (; j < j1; j++) {
        int2 ed = g_edge[j];
        float v = __int_as_float(ed.y);
        float4 ev = *(const float4*)&g_e[(size_t)ed.x * Dd + c4];
        acc.x += v * ev.x; acc.y += v * ev.y; acc.z += v * ev.z; acc.w += v * ev.w;
    }
    *(float4*)&g_tmp[w * Dd + c4] = acc;
}

// ---------------- projected positional embeddings (fp32) ----------------
__global__ void k_pos(const float* __restrict__ pos, const float* __restrict__ u_in_w,
                      const float* __restrict__ i_in_w) {
    int bid = blockIdx.x;
    int set = bid / 35;
    int r = bid % 35;
    const float* w = set ? i_in_w : u_in_w;
    const float* prow;
    float* out;
    if (r == 0)      { prow = pos;                 w += 0;           out = &g_posQ0[set * Dd]; }
    else if (r < 18) { int l = r - 1;  prow = pos + l * Dd; w += Dd * Dd;     out = &g_posK[(set * Lh + l) * Dd]; }
    else             { int l = r - 18; prow = pos + l * Dd; w += 2 * Dd * Dd; out = &g_posV[(set * Lh + l) * Dd]; }
    __shared__ float p[Dd];
    p[threadIdx.x] = prow[threadIdx.x];
    __syncthreads();
    int j = threadIdx.x;
    float acc = 0.f;
    #pragma unroll 4
    for (int k = 0; k < Dd; k++) acc += p[k] * w[j * 128 + k];
    out[j] = acc;
}

// ---------------- weight prep: fp32 -> {hi,lo} bf16, plain row-major ------------
__global__ void k_prep(const float* __restrict__ u_in_w, const float* __restrict__ i_in_w,
                       const float* __restrict__ u_out_w, const float* __restrict__ i_out_w) {
    int m = blockIdx.x;
    const float* src;
    switch (m) {
        case 0: src = u_in_w; break;
        case 1: src = u_in_w + 16384; break;
        case 2: src = u_in_w + 32768; break;
        case 3: src = i_in_w; break;
        case 4: src = i_in_w + 16384; break;
        case 5: src = i_in_w + 32768; break;
        case 6: src = u_out_w; break;
        default: src = i_out_w; break;
    }
    for (int idx = threadIdx.x; idx < 16384; idx += 256) {
        float x = src[idx];
        __nv_bfloat16 h = __float2bfloat16(x);
        __nv_bfloat16 l = __float2bfloat16(x - __bfloat162float(h));
        g_Bh[m * 16384 + idx] = h;
        g_Bl[m * 16384 + idx] = l;
    }
}

// ---------------- fused in-projection: single-pass bf16, all outputs bf16 -------
// j: 0=Qu 1=Ku 2=Vu 3=Qi 4=Ki 5=Vi.  Pure-set tiles skip the other set's Q.
// smem: Ah[128][136] + Bs[128][136] bf16 = 69632 B -> 3 CTAs/SM
__global__ void __launch_bounds__(256) k_mma_in(const float* __restrict__ u_in_b,
                                                const float* __restrict__ i_in_b) {
    extern __shared__ __align__(16) __nv_bfloat16 smp[];
    __nv_bfloat16* AhS = smp;
    __nv_bfloat16* BsS = smp + 128 * ASTRIDE;
    const uint32_t ahA = smem_to_u32(AhS), bA = smem_to_u32(BsS);
    const int t = threadIdx.x, lane = t & 31, wid = t >> 5;
    const int warp_m = wid >> 2, warp_n = wid & 3;
    const int row0 = blockIdx.x * 128;

    int skipj = -1;
    if (row0 + 128 <= Uu) skipj = 3;        // pure user tile: no Qi
    else if (row0 >= Uu)  skipj = 0;        // pure item tile: no Qu

    stage_Ah(AhS, g_tmp, row0, t);

    for (int j = 0; j < 6; j++) {
        if (j == skipj) continue;
        float acc[16][4];
        #pragma unroll
        for (int i = 0; i < 16; i++) { acc[i][0] = 0.f; acc[i][1] = 0.f; acc[i][2] = 0.f; acc[i][3] = 0.f; }

        __syncthreads();
        stage_B(BsS, &g_Bh[j * 16384], t);
        __syncthreads();
        mma_phase(ahA, 0, bA, warp_m, warp_n, lane, acc);   // single-pass AhBh

        const float* bias;
        __nv_bfloat16* outB;
        int qKind = -1;
        switch (j) {
            case 0: bias = u_in_b;        outB = g_Qb;        qKind = 0; break;
            case 1: bias = u_in_b + 128;  outB = g_KTb;       break;
            case 2: bias = u_in_b + 256;  outB = g_VTb;       break;
            case 3: bias = i_in_b;        outB = g_Qb;        qKind = 1; break;
            case 4: bias = i_in_b + 128;  outB = g_KTb + NnDd; break;
            default: bias = i_in_b + 256; outB = g_VTb + NnDd; break;
        }
        const int g = lane >> 2, q = lane & 3;
        #pragma unroll
        for (int tm = 0; tm < 4; tm++) {
            #pragma unroll
            for (int tn = 0; tn < 4; tn++) {
                int c_ = warp_n * 32 + tn * 8 + 2 * q;
                float2 bv = *(const float2*)&bias[c_];
                float* a4 = acc[tm * 4 + tn];
                #pragma unroll
                for (int hrow = 0; hrow < 2; hrow++) {
                    int r_ = row0 + warp_m * 64 + tm * 16 + g + hrow * 8;
                    if (qKind >= 0) {
                        bool ok = qKind ? (r_ >= Uu) : (r_ < Uu);
                        if (!ok) continue;
                    }
                    float ox = a4[hrow * 2 + 0] + bv.x;
                    float oy = a4[hrow * 2 + 1] + bv.y;
                    size_t ofs = (size_t)r_ * 128 + c_;
                    __nv_bfloat162 p = __halves2bfloat162(__float2bfloat16(ox), __float2bfloat16(oy));
                    *(__nv_bfloat162*)&outB[ofs] = p;
                }
            }
        }
    }
}

// ---------------- out-projection + residual + total; optional final output ------
// 2-pass split (AhBh + AlBh; weight-lo term dropped, ~1e-4 bounded contribution).
__global__ void __launch_bounds__(256) k_mma_out(const float* __restrict__ u_out_b,
                                                 const float* __restrict__ i_out_b,
                                                 float* __restrict__ finalOut) {
    extern __shared__ __align__(16) __nv_bfloat16 smp[];
    __nv_bfloat16* AhS = smp;
    __nv_bfloat16* AlS = smp + 128 * ASTRIDE;
    __nv_bfloat16* BsS = smp + 2 * 128 * ASTRIDE;
    const uint32_t ahA = smem_to_u32(AhS), alA = smem_to_u32(AlS), bA = smem_to_u32(BsS);
    const int t = threadIdx.x, lane = t & 31, wid = t >> 5;
    const int warp_m = wid >> 2, warp_n = wid & 3;

    const int set = (blockIdx.x >= 313) ? 1 : 0;
    const int bb = set ? (blockIdx.x - 313) : blockIdx.x;
    const int row0 = set * Uu + bb * 128;
    const int limit = set ? Nn : Uu;
    const int m = 6 + set;
    const float* bias = set ? i_out_b : u_out_b;

    stage_A(AhS, AlS, g_O, row0, limit, t);

    float acc[16][4];
    #pragma unroll
    for (int i = 0; i < 16; i++) { acc[i][0] = 0.f; acc[i][1] = 0.f; acc[i][2] = 0.f; acc[i][3] = 0.f; }

    stage_B(BsS, &g_Bh[m * 16384], t);
    __syncthreads();
    mma_phase(ahA, alA, bA, warp_m, warp_n, lane, acc);   // AhBh + AlBh

    const int g = lane >> 2, q = lane & 3;
    #pragma unroll
    for (int tm = 0; tm < 4; tm++) {
        #pragma unroll
        for (int tn = 0; tn < 4; tn++) {
            int c_ = warp_n * 32 + tn * 8 + 2 * q;
            float2 bv = *(const float2*)&bias[c_];
            float* a4 = acc[tm * 4 + tn];
            #pragma unroll
            for (int hrow = 0; hrow < 2; hrow++) {
                int r_ = row0 + warp_m * 64 + tm * 16 + g + hrow * 8;
                if (r_ >= limit) continue;
                size_t ofs = (size_t)r_ * 128 + c_;
                float2 rs = *(const float2*)&g_tmp[ofs];
                float ox = a4[hrow * 2 + 0] + bv.x + rs.x;
                float oy = a4[hrow * 2 + 1] + bv.y + rs.y;
                float2 tv = *(const float2*)&g_total[ofs];
                tv.x += ox; tv.y += oy;
                if (finalOut) {
                    *(float2*)&finalOut[ofs] = tv;
                    *(float2*)&finalOut[NnDd + ofs] = tv;
                } else {
                    *(float2*)&g_e[ofs] = make_float2(ox, oy);
                    *(float2*)&g_total[ofs] = tv;
                }
            }
        }
    }
}

// ---------------- attention: one warp per node; bf16 Q/K/V ----------------
__global__ void __launch_bounds__(256) k_attn(const int* __restrict__ samples) {
    int w = (blockIdx.x * 256 + threadIdx.x) >> 5;
    if (w >= Nn) return;
    int lane = threadIdx.x & 31;
    int set = (w < Uu) ? 0 : 1;
    const __nv_bfloat16* Kt = &g_KTb[(size_t)set * NnDd];
    const __nv_bfloat16* Vt = &g_VTb[(size_t)set * NnDd];
    const float* pk = &g_posK[set * Lh * Dd];
    const float* pv = &g_posV[set * Lh * Dd];
    const float* pq = &g_posQ0[set * Dd];
    int c4 = lane * 4;

    uint2 qu = *(const uint2*)&g_Qb[(size_t)w * Dd + c4];
    float2 q0 = __bfloat1622float2(*(__nv_bfloat162*)&qu.x);
    float2 q1 = __bfloat1622float2(*(__nv_bfloat162*)&qu.y);
    float4 pqv = *(const float4*)&pq[c4];
    float qx = q0.x + pqv.x, qy = q0.y + pqv.y, qz = q1.x + pqv.z, qw = q1.y + pqv.w;

    int sidx[Lh];
    sidx[0] = w;
    #pragma unroll
    for (int l = 1; l < Lh; l++) sidx[l] = samples[w * 16 + (l - 1)];

    const float scale = 0.17677669529663687f;
    float sc[Lh];
    #pragma unroll
    for (int b = 0; b < 4; b++) {
        uint2 ku[4]; float4 pk4[4];
        #pragma unroll
        for (int i = 0; i < 4; i++) {
            int l = b * 4 + i;
            ku[i] = *(const uint2*)&Kt[(size_t)sidx[l] * Dd + c4];
            pk4[i] = *(const float4*)&pk[l * Dd + c4];
        }
        #pragma unroll
        for (int i = 0; i < 4; i++) {
            float2 f0 = __bfloat1622float2(*(__nv_bfloat162*)&ku[i].x);
            float2 f1 = __bfloat1622float2(*(__nv_bfloat162*)&ku[i].y);
            float d = qx * (f0.x + pk4[i].x) + qy * (f0.y + pk4[i].y)
                    + qz * (f1.x + pk4[i].z) + qw * (f1.y + pk4[i].w);
            d += __shfl_xor_sync(0xffffffffu, d, 1);
            d += __shfl_xor_sync(0xffffffffu, d, 2);
            d += __shfl_xor_sync(0xffffffffu, d, 4);
            sc[b * 4 + i] = d * scale;
        }
    }
    {
        uint2 u = *(const uint2*)&Kt[(size_t)sidx[16] * Dd + c4];
        float4 pkv = *(const float4*)&pk[16 * Dd + c4];
        float2 f0 = __bfloat1622float2(*(__nv_bfloat162*)&u.x);
        float2 f1 = __bfloat1622float2(*(__nv_bfloat162*)&u.y);
        float d = qx * (f0.x + pkv.x) + qy * (f0.y + pkv.y) + qz * (f1.x + pkv.z) + qw * (f1.y + pkv.w);
        d += __shfl_xor_sync(0xffffffffu, d, 1);
        d += __shfl_xor_sync(0xffffffffu, d, 2);
        d += __shfl_xor_sync(0xffffffffu, d, 4);
        sc[16] = d * scale;
    }
    float m = sc[0];
    #pragma unroll
    for (int l = 1; l < Lh; l++) m = fmaxf(m, sc[l]);
    float s = 0.f;
    #pragma unroll
    for (int l = 0; l < Lh; l++) { sc[l] = __expf(sc[l] - m); s += sc[l]; }
    float inv = 1.f / s;

    float ox = 0.f, oy = 0.f, oz = 0.f, ow = 0.f;
    #pragma unroll
    for (int b = 0; b < 4; b++) {
        uint2 vu[4]; float4 pv4[4];
        #pragma unroll
        for (int i = 0; i < 4; i++) {
            int l = b * 4 + i;
            vu[i] = *(const uint2*)&Vt[(size_t)sidx[l] * Dd + c4];
            pv4[i] = *(const float4*)&pv[l * Dd + c4];
        }
        #pragma unroll
        for (int i = 0; i < 4; i++) {
            float wgt = sc[b * 4 + i] * inv;
            float2 f0 = __bfloat1622float2(*(__nv_bfloat162*)&vu[i].x);
            float2 f1 = __bfloat1622float2(*(__nv_bfloat162*)&vu[i].y);
            ox += wgt * (f0.x + pv4[i].x); oy += wgt * (f0.y + pv4[i].y);
            oz += wgt * (f1.x + pv4[i].z); ow += wgt * (f1.y + pv4[i].w);
        }
    }
    {
        float wgt = sc[16] * inv;
        uint2 u = *(const uint2*)&Vt[(size_t)sidx[16] * Dd + c4];
        float4 pvv = *(const float4*)&pv[16 * Dd + c4];
        float2 f0 = __bfloat1622float2(*(__nv_bfloat162*)&u.x);
        float2 f1 = __bfloat1622float2(*(__nv_bfloat162*)&u.y);
        ox += wgt * (f0.x + pvv.x); oy += wgt * (f0.y + pvv.y);
        oz += wgt * (f1.x + pvv.z); ow += wgt * (f1.y + pvv.w);
    }
    *(float4*)&g_O[w * Dd + c4] = make_float4(ox, oy, oz, ow);
}

extern "C" void kernel_launch(void* const* d_in, const int* in_sizes, int n_in,
                              void* d_out, int out_size) {
    (void)in_sizes; (void)n_in; (void)out_size;
    const int*   adj_rows = (const int*)d_in[0];
    const int*   adj_cols = (const int*)d_in[1];
    const float* adj_vals = (const float*)d_in[2];
    const int*   samples  = (const int*)d_in[3];
    const float* user_emb = (const float*)d_in[4];
    const float* item_emb = (const float*)d_in[5];
    const float* pos_emb  = (const float*)d_in[6];
    const float* u_in_w   = (const float*)d_in[7];
    const float* u_in_b   = (const float*)d_in[8];
    const float* u_out_w  = (const float*)d_in[9];
    const float* u_out_b  = (const float*)d_in[10];
    const float* i_in_w   = (const float*)d_in[11];
    const float* i_in_b   = (const float*)d_in[12];
    const float* i_out_w  = (const float*)d_in[13];
    const float* i_out_b  = (const float*)d_in[14];
    float* out = (float*)d_out;

    const int SMB_IN  = 2 * 128 * ASTRIDE * (int)sizeof(__nv_bfloat16);  // 69632
    const int SMB_OUT = 3 * 128 * ASTRIDE * (int)sizeof(__nv_bfloat16);  // 104448
    cudaFuncSetAttribute(k_mma_in,  cudaFuncAttributeMaxDynamicSharedMemorySize, SMB_IN);
    cudaFuncSetAttribute(k_mma_out, cudaFuncAttributeMaxDynamicSharedMemorySize, SMB_OUT);

    k_init<<<(NnDd / 4 + 255) / 256, 256>>>((const float4*)user_emb, (const float4*)item_emb);
    k_hist<<<(Ee + 255) / 256, 256>>>(adj_rows);
    k_scan<<<1, 1024>>>();                       // also re-zeroes g_cnt
    k_scatter<<<(Ee + 255) / 256, 256>>>(adj_rows, adj_cols, adj_vals);

    for (int blk = 0; blk < 2; blk++) {
        k_spmm<<<(Nn * 32) / 256, 256>>>();
        if (blk == 0) {
            k_pos<<<70, 128>>>(pos_emb, u_in_w, i_in_w);
            k_prep<<<8, 256>>>(u_in_w, i_in_w, u_out_w, i_out_w);
        }
        k_mma_in<<<Nn / 128, 256, SMB_IN>>>(u_in_b, i_in_b);
        k_attn<<<(Nn * 32) / 256, 256>>>(samples);
        k_mma_out<<<626, 256, SMB_OUT>>>(u_out_b, i_out_b, (blk == 1) ? out : nullptr);
    }
}